// round 1
// baseline (speedup 1.0000x reference)
#include <cuda_runtime.h>
#include <math.h>

// Problem constants
#define BB_ 32
#define NN_ 49
#define DD_ 512
#define HH_ 8
#define DKK_ 64
#define MM_ (BB_*NN_)      // 1568
#define NRELV_ 14
#define EPSV_ 1e-5f
#define SCALEV_ 0.125f     // 1/sqrt(64)

// ---------------- device scratch (no allocations allowed) ----------------
__device__ __align__(256) float g_hconv[MM_*DD_];
__device__ __align__(256) float g_eq[MM_*DD_];
__device__ __align__(256) float g_ek[MM_*DD_];
__device__ __align__(256) float g_ev[MM_*DD_];
__device__ __align__(256) float g_eqcat[MM_*1280];
__device__ __align__(256) float g_ekcat[MM_*1280];
__device__ __align__(256) float g_v[MM_*DD_];
__device__ __align__(256) float g_att[MM_*DD_];
__device__ __align__(256) float g_convWt[9*512*512];
__device__ __align__(256) float g_Bq[512*1280];
__device__ __align__(256) float g_Bk[512*1280];
__device__ __align__(256) float g_biasq[1280];
__device__ __align__(256) float g_biask[1280];
__device__ float g_sums[1024];
__device__ float g_mu[512];
__device__ float g_is[512];
__device__ float g_wr2g[512];
__device__ float g_reg[NRELV_];
__device__ float g_c0[1];
__device__ float g_gate[MM_*NN_];

__device__ __forceinline__ float wsum(float v) {
#pragma unroll
    for (int o = 16; o > 0; o >>= 1) v += __shfl_xor_sync(0xffffffffu, v, o);
    return v;
}

// ---------------- tiny precompute: folded gate vectors ----------------
__global__ void rea_k0(const float* __restrict__ Wr2, const float* __restrict__ Wproj,
                       const float* __restrict__ Wg, const float* __restrict__ rel,
                       const float* __restrict__ br2, const float* __restrict__ bproj,
                       const float* __restrict__ bgate) {
    __shared__ float wg_s[512];
    __shared__ float wpg_s[64];
    int t = threadIdx.x;
    wg_s[t] = Wg[t];
    __syncthreads();
    float a = 0.f;
    for (int j = 0; j < 512; j++) a += Wr2[(size_t)t*512 + j] * wg_s[j];
    g_wr2g[t] = a;
    if (t < 64) {
        float s = 0.f;
        for (int j = 0; j < 512; j++) s += Wproj[(size_t)t*512 + j] * wg_s[j];
        wpg_s[t] = s;
    }
    __syncthreads();
    if (t < NRELV_) {
        float s = 0.f;
        for (int d = 0; d < 64; d++) s += rel[t*64 + d] * wpg_s[d];
        g_reg[t] = s;
    }
    if (t == 0) {
        float s = bgate[0];
        for (int j = 0; j < 512; j++) s += (br2[j] + bproj[j]) * wg_s[j];
        g_c0[0] = s;
    }
}

// ---------------- weight repacks ----------------
__global__ void rea_repack_conv(const float* __restrict__ convW) {
    int idx = blockIdx.x*blockDim.x + threadIdx.x;
    if (idx >= 9*512*512) return;
    int o = idx & 511;
    int c = (idx >> 9) & 511;
    int tap = idx >> 18;
    g_convWt[idx] = convW[((size_t)o*512 + c)*9 + tap];
}

__global__ void rea_repack_bcat(const float* __restrict__ Wq, const float* __restrict__ Wk,
                                const float* __restrict__ Wc1, const float* __restrict__ Wr1,
                                const float* __restrict__ bq, const float* __restrict__ bk) {
    int idx = blockIdx.x*blockDim.x + threadIdx.x;
    if (idx < 512*1280) {
        int k = idx / 1280, n = idx - k*1280;
        float vq, vk;
        if (n < 512)       { vq = Wq[(size_t)k*512 + n];              vk = Wk[(size_t)k*512 + n]; }
        else if (n < 768)  { vq = Wc1[(size_t)k*256 + (n-512)];       vk = Wc1[(size_t)(k+512)*256 + (n-512)]; }
        else               { vq = Wr1[(size_t)k*512 + (n-768)];       vk = Wr1[(size_t)(k+512)*512 + (n-768)]; }
        g_Bq[idx] = vq; g_Bk[idx] = vk;
    }
    if (idx < 1280) {
        g_biasq[idx] = idx < 512 ? bq[idx] : 0.f;
        g_biask[idx] = idx < 512 ? bk[idx] : 0.f;
    }
}

__global__ void rea_zero_stats() {
    int i = blockIdx.x*blockDim.x + threadIdx.x;
    if (i < 1024) g_sums[i] = 0.f;
}

// ---------------- fp32 tiled GEMM (64x64x16, 128 threads, 8x4 microtile) ----------------
// A row-major [M,K] (or implicit im2col of queries when CONV), B row-major [K,N],
// C row-major [M,N] = A*B + bias.
template <bool CONV>
__global__ void rea_gemm64(const float* __restrict__ A, const float* __restrict__ Bm,
                           const float* __restrict__ bias, float* __restrict__ C,
                           int M, int N, int K) {
    __shared__ float As[16][64];
    __shared__ float Bs[16][64];
    int tid = threadIdx.x;
    int tx = tid & 15, ty = tid >> 4;
    int m0 = blockIdx.y*64, n0 = blockIdx.x*64;
    float acc[8][4];
#pragma unroll
    for (int i = 0; i < 8; i++)
#pragma unroll
        for (int j = 0; j < 4; j++) acc[i][j] = 0.f;

    for (int k0 = 0; k0 < K; k0 += 16) {
#pragma unroll
        for (int i = 0; i < 2; i++) {
            int li = tid*2 + i;
            int r = li >> 2, cg = li & 3;
            float4 v = make_float4(0.f, 0.f, 0.f, 0.f);
            int gm = m0 + r;
            if (!CONV) {
                if (gm < M) v = *(const float4*)(A + (size_t)gm*K + k0 + cg*4);
            } else {
                if (gm < M) {
                    int bb = gm / 49, pos = gm - bb*49;
                    int kkg = k0 + cg*4;
                    int tap = kkg >> 9, c = kkg & 511;
                    int ii = pos/7 + tap/3 - 1;
                    int jj = pos%7 + tap%3 - 1;
                    if (ii >= 0 && ii < 7 && jj >= 0 && jj < 7)
                        v = *(const float4*)(A + ((size_t)bb*49 + ii*7 + jj)*512 + c);
                }
            }
            int kb = cg*4;
            As[kb+0][r] = v.x; As[kb+1][r] = v.y; As[kb+2][r] = v.z; As[kb+3][r] = v.w;
        }
#pragma unroll
        for (int i = 0; i < 2; i++) {
            int li = tid*2 + i;
            int r = li >> 4, cg = li & 15;
            *(float4*)&Bs[r][cg*4] = *(const float4*)(Bm + (size_t)(k0 + r)*N + n0 + cg*4);
        }
        __syncthreads();
#pragma unroll
        for (int kk = 0; kk < 16; kk++) {
            float4 a0 = *(float4*)&As[kk][ty*8];
            float4 a1 = *(float4*)&As[kk][ty*8 + 4];
            float4 bv = *(float4*)&Bs[kk][tx*4];
            float a[8] = {a0.x, a0.y, a0.z, a0.w, a1.x, a1.y, a1.z, a1.w};
            float bb4[4] = {bv.x, bv.y, bv.z, bv.w};
#pragma unroll
            for (int i = 0; i < 8; i++)
#pragma unroll
                for (int j = 0; j < 4; j++) acc[i][j] += a[i]*bb4[j];
        }
        __syncthreads();
    }
    float4 bb = bias ? *(const float4*)(bias + n0 + tx*4) : make_float4(0.f, 0.f, 0.f, 0.f);
#pragma unroll
    for (int i = 0; i < 8; i++) {
        int gm = m0 + ty*8 + i;
        if (gm < M) {
            float4 o;
            o.x = acc[i][0] + bb.x; o.y = acc[i][1] + bb.y;
            o.z = acc[i][2] + bb.z; o.w = acc[i][3] + bb.w;
            *(float4*)(C + (size_t)gm*N + n0 + tx*4) = o;
        }
    }
}

// ---------------- batchnorm stats + finalize + eq/ek/ev ----------------
__global__ void rea_bn_stats() {
    __shared__ float ss[512], sq[512];
    int tid = threadIdx.x;
    for (int c = tid; c < 512; c += 256) { ss[c] = 0.f; sq[c] = 0.f; }
    __syncthreads();
    int r0 = blockIdx.x*32;
    for (int r = r0; r < r0 + 32; r++) {
        for (int c = tid; c < 512; c += 256) {
            float v = g_hconv[(size_t)r*512 + c];
            ss[c] += v; sq[c] += v*v;
        }
    }
    __syncthreads();
    for (int c = tid; c < 512; c += 256) {
        atomicAdd(&g_sums[c], ss[c]);
        atomicAdd(&g_sums[512 + c], sq[c]);
    }
}

__global__ void rea_bn_fin() {
    int t = threadIdx.x;
    float s = g_sums[t], q = g_sums[512 + t];
    float mu = s * (1.f/1568.f);
    float var = q * (1.f/1568.f) - mu*mu;
    g_mu[t] = mu;
    g_is[t] = rsqrtf(var + EPSV_);
}

__global__ void rea_eqkv(const float* __restrict__ Q, const float* __restrict__ Kin,
                         const float* __restrict__ Vin) {
    int idx = blockIdx.x*blockDim.x + threadIdx.x;
    if (idx >= MM_*DD_) return;
    int c = idx & 511;
    float xn = (g_hconv[idx] - g_mu[c]) * g_is[c];
    xn = fmaxf(xn, 0.f);
    g_eq[idx] = xn + Q[idx];
    g_ek[idx] = xn + Kin[idx];
    g_ev[idx] = xn + Vin[idx];
}

// ---------------- per-pair gate kernel ----------------
__global__ void rea_pair(const float* __restrict__ Wc2, const float* __restrict__ bc1,
                         const float* __restrict__ gc, const float* __restrict__ bcln,
                         const float* __restrict__ bc2, const float* __restrict__ br1,
                         const float* __restrict__ gr, const float* __restrict__ brln) {
    __shared__ float s_pa1[256], s_gc[256], s_bcl[256];
    __shared__ float s_par[512], s_gr[512], s_brl[512], s_w2g[512];
    __shared__ float s_wc2t[14*256];
    __shared__ float s_bc2[16], s_reg[16];
    int m = blockIdx.x;
    int b = m / 49;
    int t = threadIdx.x;
    const float* eqr = g_eqcat + (size_t)m*1280;
    s_pa1[t] = eqr[512 + t] + bc1[t];
    s_gc[t] = gc[t]; s_bcl[t] = bcln[t];
    for (int j = t; j < 512; j += 256) {
        s_par[j] = eqr[768 + j] + br1[j];
        s_gr[j] = gr[j]; s_brl[j] = brln[j]; s_w2g[j] = g_wr2g[j];
    }
    for (int idx = t; idx < 14*256; idx += 256) {
        int tt = idx >> 8, j = idx & 255;
        s_wc2t[idx] = Wc2[j*14 + tt];
    }
    if (t < NRELV_) { s_bc2[t] = bc2[t]; s_reg[t] = g_reg[t]; }
    __syncthreads();
    float c0 = g_c0[0];
    int w = t >> 5, l = t & 31;
    for (int k = w; k < 49; k += 8) {
        const float* ekr = g_ekcat + (size_t)(b*49 + k)*1280;
        // ---- channel-scorer branch: LN(256) -> relu -> @Wc2 -> softmax(14) ----
        float xc[8]; float s = 0.f;
#pragma unroll
        for (int jj = 0; jj < 8; jj++) { int j = l + 32*jj; xc[jj] = s_pa1[j] + ekr[512 + j]; s += xc[jj]; }
        s = wsum(s);
        float mean = s * (1.f/256.f);
        float vs = 0.f;
#pragma unroll
        for (int jj = 0; jj < 8; jj++) { float d = xc[jj] - mean; vs += d*d; }
        vs = wsum(vs);
        float rs = rsqrtf(vs*(1.f/256.f) + EPSV_);
        float lg[14];
#pragma unroll
        for (int tt = 0; tt < 14; tt++) lg[tt] = 0.f;
#pragma unroll
        for (int jj = 0; jj < 8; jj++) {
            int j = l + 32*jj;
            float y = (xc[jj] - mean)*rs*s_gc[j] + s_bcl[j];
            y = fmaxf(y, 0.f);
#pragma unroll
            for (int tt = 0; tt < 14; tt++) lg[tt] += y * s_wc2t[tt*256 + j];
        }
#pragma unroll
        for (int o = 16; o > 0; o >>= 1) {
#pragma unroll
            for (int tt = 0; tt < 14; tt++) lg[tt] += __shfl_xor_sync(0xffffffffu, lg[tt], o);
        }
        float mx = -1e30f;
#pragma unroll
        for (int tt = 0; tt < 14; tt++) { lg[tt] += s_bc2[tt]; mx = fmaxf(mx, lg[tt]); }
        float se = 0.f, dg = 0.f;
#pragma unroll
        for (int tt = 0; tt < 14; tt++) { float e = expf(lg[tt] - mx); se += e; dg += e*s_reg[tt]; }
        float proj = dg / se * (1.f/(1.f + 1e-8f));   // top_k over all 14 == identity
        // ---- relation branch: LN(512) -> relu -> dot(wr2g) ----
        float xr[16]; float sr = 0.f;
#pragma unroll
        for (int jj = 0; jj < 16; jj++) { int j = l + 32*jj; xr[jj] = s_par[j] + ekr[768 + j]; sr += xr[jj]; }
        sr = wsum(sr);
        float mr = sr * (1.f/512.f);
        float vr = 0.f;
#pragma unroll
        for (int jj = 0; jj < 16; jj++) { float d = xr[jj] - mr; vr += d*d; }
        vr = wsum(vr);
        float rsr = rsqrtf(vr*(1.f/512.f) + EPSV_);
        float dr = 0.f;
#pragma unroll
        for (int jj = 0; jj < 16; jj++) {
            int j = l + 32*jj;
            float y = (xr[jj] - mr)*rsr*s_gr[j] + s_brl[j];
            y = fmaxf(y, 0.f);
            dr += y * s_w2g[j];
        }
        dr = wsum(dr);
        if (l == 0) {
            float ga = dr + proj + c0;
            g_gate[(size_t)m*49 + k] = 1.f/(1.f + expf(-ga));
        }
    }
}

// ---------------- attention: logits * (1+gate), softmax(49), @V ----------------
__global__ void rea_attn(float* __restrict__ out) {
    int m = blockIdx.x, b = m / 49;
    int h = threadIdx.x >> 5, l = threadIdx.x & 31;
    __shared__ float lg[8][64];
    __shared__ float gs[49];
    if (threadIdx.x < 49) gs[threadIdx.x] = g_gate[(size_t)m*49 + threadIdx.x];
    float2 q2 = *(const float2*)(g_eqcat + (size_t)m*1280 + h*64 + l*2);
    __syncthreads();
    for (int k = 0; k < 49; k++) {
        float2 k2 = *(const float2*)(g_ekcat + (size_t)(b*49 + k)*1280 + h*64 + l*2);
        float d = q2.x*k2.x + q2.y*k2.y;
        d = wsum(d);
        if (l == 0) lg[h][k] = d * SCALEV_ * (1.f + gs[k]);
    }
    __syncwarp();
    float v0 = lg[h][l];
    float v1 = (l < 17) ? lg[h][l + 32] : -1e30f;
    float mx = fmaxf(v0, v1);
#pragma unroll
    for (int o = 16; o > 0; o >>= 1) mx = fmaxf(mx, __shfl_xor_sync(0xffffffffu, mx, o));
    float e0 = expf(v0 - mx);
    float e1 = (l < 17) ? expf(v1 - mx) : 0.f;
    float ssum = wsum(e0 + e1);
    float inv = 1.f / ssum;
    lg[h][l] = e0 * inv;
    if (l < 17) lg[h][l + 32] = e1 * inv;
    __syncwarp();
    float2 acc = make_float2(0.f, 0.f);
    for (int k = 0; k < 49; k++) {
        float wv = lg[h][k];
        float2 v2 = *(const float2*)(g_v + (size_t)(b*49 + k)*512 + h*64 + l*2);
        acc.x += wv*v2.x; acc.y += wv*v2.y;
    }
    *(float2*)(out + (size_t)m*512 + h*64 + l*2) = acc;
}

// ---------------- launch ----------------
extern "C" void kernel_launch(void* const* d_in, const int* in_sizes, int n_in,
                              void* d_out, int out_size) {
    const float* Q     = (const float*)d_in[0];
    const float* Kin   = (const float*)d_in[1];
    const float* Vin   = (const float*)d_in[2];
    const float* Wq    = (const float*)d_in[3];
    const float* bq    = (const float*)d_in[4];
    const float* Wk    = (const float*)d_in[5];
    const float* bk    = (const float*)d_in[6];
    const float* Wv    = (const float*)d_in[7];
    const float* bv    = (const float*)d_in[8];
    const float* Wo    = (const float*)d_in[9];
    const float* bo    = (const float*)d_in[10];
    const float* rel   = (const float*)d_in[11];
    const float* Wproj = (const float*)d_in[12];
    const float* bproj = (const float*)d_in[13];
    const float* Wgate = (const float*)d_in[14];
    const float* bgate = (const float*)d_in[15];
    const float* Wc1   = (const float*)d_in[16];
    const float* bc1   = (const float*)d_in[17];
    const float* gc    = (const float*)d_in[18];
    const float* bcln  = (const float*)d_in[19];
    const float* Wc2   = (const float*)d_in[20];
    const float* bc2   = (const float*)d_in[21];
    const float* Wr1   = (const float*)d_in[22];
    const float* br1   = (const float*)d_in[23];
    const float* gr    = (const float*)d_in[24];
    const float* brln  = (const float*)d_in[25];
    const float* Wr2   = (const float*)d_in[26];
    const float* br2   = (const float*)d_in[27];
    const float* convW = (const float*)d_in[28];
    const float* convb = (const float*)d_in[29];

    void *p_hconv, *p_eq, *p_ek, *p_ev, *p_eqcat, *p_ekcat, *p_v, *p_att;
    void *p_convWt, *p_Bq, *p_Bk, *p_biasq, *p_biask;
    cudaGetSymbolAddress(&p_hconv, g_hconv);
    cudaGetSymbolAddress(&p_eq, g_eq);
    cudaGetSymbolAddress(&p_ek, g_ek);
    cudaGetSymbolAddress(&p_ev, g_ev);
    cudaGetSymbolAddress(&p_eqcat, g_eqcat);
    cudaGetSymbolAddress(&p_ekcat, g_ekcat);
    cudaGetSymbolAddress(&p_v, g_v);
    cudaGetSymbolAddress(&p_att, g_att);
    cudaGetSymbolAddress(&p_convWt, g_convWt);
    cudaGetSymbolAddress(&p_Bq, g_Bq);
    cudaGetSymbolAddress(&p_Bk, g_Bk);
    cudaGetSymbolAddress(&p_biasq, g_biasq);
    cudaGetSymbolAddress(&p_biask, g_biask);

    rea_zero_stats<<<4, 256>>>();
    rea_k0<<<1, 512>>>(Wr2, Wproj, Wgate, rel, br2, bproj, bgate);
    rea_repack_conv<<<(9*512*512 + 255)/256, 256>>>(convW);
    rea_repack_bcat<<<(512*1280 + 255)/256, 256>>>(Wq, Wk, Wc1, Wr1, bq, bk);

    // conv3x3 as implicit GEMM: [1568, 512] = im2col(Q)[1568,4608] @ convWt[4608,512] + convb
    rea_gemm64<true><<<dim3(8, 25), 128>>>(Q, (const float*)p_convWt, convb,
                                           (float*)p_hconv, MM_, 512, 4608);
    rea_bn_stats<<<49, 256>>>();
    rea_bn_fin<<<1, 512>>>();
    rea_eqkv<<<(MM_*DD_ + 255)/256, 256>>>(Q, Kin, Vin);

    // fused token projections: eq @ [Wq | Wc1_top | Wr1_top], ek @ [Wk | Wc1_bot | Wr1_bot]
    rea_gemm64<false><<<dim3(20, 25), 128>>>((const float*)p_eq, (const float*)p_Bq,
                                             (const float*)p_biasq, (float*)p_eqcat,
                                             MM_, 1280, 512);
    rea_gemm64<false><<<dim3(20, 25), 128>>>((const float*)p_ek, (const float*)p_Bk,
                                             (const float*)p_biask, (float*)p_ekcat,
                                             MM_, 1280, 512);
    rea_gemm64<false><<<dim3(8, 25), 128>>>((const float*)p_ev, Wv, bv,
                                            (float*)p_v, MM_, 512, 512);

    rea_pair<<<MM_, 256>>>(Wc2, bc1, gc, bcln, bc2, br1, gr, brln);
    rea_attn<<<MM_, 256>>>((float*)p_att);

    rea_gemm64<false><<<dim3(8, 25), 128>>>((const float*)p_att, Wo, bo,
                                            (float*)d_out, MM_, 512, 512);
}

// round 2
// speedup vs baseline: 1.5933x; 1.5933x over previous
#include <cuda_runtime.h>
#include <math.h>
#include <stdint.h>

// Problem constants
#define BB_ 32
#define NN_ 49
#define DD_ 512
#define MM_ (BB_*NN_)      // 1568
#define NRELV_ 14
#define EPSV_ 1e-5f
#define SCALEV_ 0.125f     // 1/sqrt(64)

// ---------------- device scratch (no allocations allowed) ----------------
__device__ __align__(256) float g_hconv[MM_*DD_];
__device__ __align__(256) float g_qr[MM_*DD_];
__device__ __align__(256) float g_eq[MM_*DD_];
__device__ __align__(256) float g_ek[MM_*DD_];
__device__ __align__(256) float g_ev[MM_*DD_];
__device__ __align__(256) float g_eqcat[MM_*1280];
__device__ __align__(256) float g_ekcat[MM_*1280];
__device__ __align__(256) float g_v[MM_*DD_];
__device__ __align__(256) float g_att[MM_*DD_];
__device__ __align__(256) float g_convWt[9*512*512];
__device__ __align__(256) float g_Bq[512*1280];
__device__ __align__(256) float g_Bk[512*1280];
__device__ __align__(256) float g_Wvr[512*512];
__device__ __align__(256) float g_Wor[512*512];
__device__ __align__(256) float g_biasq[1280];
__device__ __align__(256) float g_biask[1280];
__device__ float g_sums[1024];
__device__ float g_mu[512];
__device__ float g_is[512];
__device__ float g_wr2g[512];
__device__ float g_reg[NRELV_];
__device__ float g_c0[1];
__device__ float g_gate[MM_*NN_];

__device__ __forceinline__ float wsum(float v) {
#pragma unroll
    for (int o = 16; o > 0; o >>= 1) v += __shfl_xor_sync(0xffffffffu, v, o);
    return v;
}

__device__ __forceinline__ float to_tf32(float x) {
    uint32_t u;
    asm("cvt.rna.tf32.f32 %0, %1;" : "=r"(u) : "f"(x));
    return __uint_as_float(u);
}

__device__ __forceinline__ void mma_tf32(float* c,
                                         uint32_t a0, uint32_t a1, uint32_t a2, uint32_t a3,
                                         uint32_t b0, uint32_t b1) {
    asm volatile("mma.sync.aligned.m16n8k8.row.col.f32.tf32.tf32.f32 "
                 "{%0,%1,%2,%3}, {%4,%5,%6,%7}, {%8,%9}, {%0,%1,%2,%3};"
                 : "+f"(c[0]), "+f"(c[1]), "+f"(c[2]), "+f"(c[3])
                 : "r"(a0), "r"(a1), "r"(a2), "r"(a3), "r"(b0), "r"(b1));
}

// ---------------- tiny precompute: folded gate vectors ----------------
__global__ void rea_k0(const float* __restrict__ Wr2, const float* __restrict__ Wproj,
                       const float* __restrict__ Wg, const float* __restrict__ rel,
                       const float* __restrict__ br2, const float* __restrict__ bproj,
                       const float* __restrict__ bgate) {
    __shared__ float wg_s[512];
    __shared__ float wpg_s[64];
    int t = threadIdx.x;
    wg_s[t] = Wg[t];
    __syncthreads();
    float a = 0.f;
    for (int j = 0; j < 512; j++) a += Wr2[(size_t)t*512 + j] * wg_s[j];
    g_wr2g[t] = a;
    if (t < 64) {
        float s = 0.f;
        for (int j = 0; j < 512; j++) s += Wproj[(size_t)t*512 + j] * wg_s[j];
        wpg_s[t] = s;
    }
    __syncthreads();
    if (t < NRELV_) {
        float s = 0.f;
        for (int d = 0; d < 64; d++) s += rel[t*64 + d] * wpg_s[d];
        g_reg[t] = s;
    }
    if (t == 0) {
        float s = bgate[0];
        for (int j = 0; j < 512; j++) s += (br2[j] + bproj[j]) * wg_s[j];
        g_c0[0] = s;
    }
}

// ---------------- weight repacks (rounded to tf32) ----------------
__global__ void rea_repack_conv(const float* __restrict__ convW) {
    int idx = blockIdx.x*blockDim.x + threadIdx.x;
    if (idx >= 9*512*512) return;
    int o = idx & 511;
    int c = (idx >> 9) & 511;
    int tap = idx >> 18;
    g_convWt[idx] = to_tf32(convW[((size_t)o*512 + c)*9 + tap]);
}

__global__ void rea_repack_bcat(const float* __restrict__ Wq, const float* __restrict__ Wk,
                                const float* __restrict__ Wc1, const float* __restrict__ Wr1,
                                const float* __restrict__ bq, const float* __restrict__ bk) {
    int idx = blockIdx.x*blockDim.x + threadIdx.x;
    if (idx < 512*1280) {
        int k = idx / 1280, n = idx - k*1280;
        float vq, vk;
        if (n < 512)       { vq = Wq[(size_t)k*512 + n];              vk = Wk[(size_t)k*512 + n]; }
        else if (n < 768)  { vq = Wc1[(size_t)k*256 + (n-512)];       vk = Wc1[(size_t)(k+512)*256 + (n-512)]; }
        else               { vq = Wr1[(size_t)k*512 + (n-768)];       vk = Wr1[(size_t)(k+512)*512 + (n-768)]; }
        g_Bq[idx] = to_tf32(vq); g_Bk[idx] = to_tf32(vk);
    }
    if (idx < 1280) {
        g_biasq[idx] = idx < 512 ? bq[idx] : 0.f;
        g_biask[idx] = idx < 512 ? bk[idx] : 0.f;
    }
}

__global__ void rea_round_w(const float* __restrict__ Wv, const float* __restrict__ Wo) {
    int idx = blockIdx.x*blockDim.x + threadIdx.x;
    if (idx >= 512*512) return;
    g_Wvr[idx] = to_tf32(Wv[idx]);
    g_Wor[idx] = to_tf32(Wo[idx]);
}

__global__ void rea_round_q(const float* __restrict__ Q) {
    int idx = blockIdx.x*blockDim.x + threadIdx.x;
    if (idx >= MM_*DD_) return;
    g_qr[idx] = to_tf32(Q[idx]);
}

__global__ void rea_zero_stats() {
    int i = blockIdx.x*blockDim.x + threadIdx.x;
    if (i < 1024) g_sums[i] = 0.f;
}

__global__ void rea_zero_hconv() {
    int i = blockIdx.x*blockDim.x + threadIdx.x;
    if (i < MM_*DD_) g_hconv[i] = 0.f;
}

// ---------------- TF32 tensor-core GEMM ----------------
// Block tile 128x64, BK=16, 256 threads = 8 warps in 4(M) x 2(N), warp tile 32x32.
// A row-major [M,lda] (or implicit im2col when CONV), B row-major [K,N].
// When ATOMIC: atomicAdd into C (pre-zeroed), bias added only by blockIdx.z==0.
#define BMT 128
#define BNT 64
#define BKT 16
#define ASTR 136
#define BSTR 72

template <bool CONV, bool ATOMIC>
__global__ void __launch_bounds__(256, 2)
rea_mma(const float* __restrict__ A, const float* __restrict__ Bm,
        const float* __restrict__ bias, float* __restrict__ C,
        int M, int N, int K /* = K per split */) {
    __shared__ float As[BKT*ASTR];
    __shared__ float Bs[BKT*BSTR];
    int tid = threadIdx.x;
    int lane = tid & 31, warp = tid >> 5;
    int wm = (warp & 3) * 32, wn = (warp >> 2) * 32;
    int g = lane >> 2, t4 = lane & 3;
    int m0 = blockIdx.y * BMT, n0 = blockIdx.x * BNT;
    int kbase = blockIdx.z * K;

    float acc[2][4][4];
#pragma unroll
    for (int i = 0; i < 2; i++)
#pragma unroll
        for (int j = 0; j < 4; j++)
#pragma unroll
            for (int q = 0; q < 4; q++) acc[i][j][q] = 0.f;

    int am = tid & 127;      // m within tile
    int akg0 = tid >> 7;     // 0..1 (second iter adds 2)
    int bkr = tid >> 4;      // 0..15
    int bnr = tid & 15;      // 0..15

    int KT = K / BKT;
    float4 ra[2], rb;

    // ---- prefetch tile 0 ----
    {
        int gm = m0 + am;
#pragma unroll
        for (int it = 0; it < 2; it++) {
            int kk = kbase + (akg0 + it*2)*4;
            float4 v = make_float4(0.f, 0.f, 0.f, 0.f);
            if (gm < M) {
                if (!CONV) {
                    v = *(const float4*)(A + (size_t)gm*K + kk);
                } else {
                    int bb2 = gm / 49, pos = gm - bb2*49;
                    int tap = kk >> 9, c = kk & 511;
                    int ii = pos/7 + tap/3 - 1, jj = pos%7 + tap%3 - 1;
                    if (ii >= 0 && ii < 7 && jj >= 0 && jj < 7)
                        v = *(const float4*)(A + ((size_t)bb2*49 + ii*7 + jj)*512 + c);
                }
            }
            ra[it] = v;
        }
        rb = *(const float4*)(Bm + (size_t)(kbase + bkr)*N + n0 + bnr*4);
    }

    for (int kt = 0; kt < KT; kt++) {
        // store current tile to smem
#pragma unroll
        for (int it = 0; it < 2; it++) {
            int kg = akg0 + it*2;
            As[(kg*4 + 0)*ASTR + am] = ra[it].x;
            As[(kg*4 + 1)*ASTR + am] = ra[it].y;
            As[(kg*4 + 2)*ASTR + am] = ra[it].z;
            As[(kg*4 + 3)*ASTR + am] = ra[it].w;
        }
        *(float4*)&Bs[bkr*BSTR + bnr*4] = rb;
        __syncthreads();

        // prefetch next tile
        if (kt + 1 < KT) {
            int gm = m0 + am;
            int k0n = kbase + (kt + 1)*BKT;
#pragma unroll
            for (int it = 0; it < 2; it++) {
                int kk = k0n + (akg0 + it*2)*4;
                float4 v = make_float4(0.f, 0.f, 0.f, 0.f);
                if (gm < M) {
                    if (!CONV) {
                        v = *(const float4*)(A + (size_t)gm*K + kk);
                    } else {
                        int bb2 = gm / 49, pos = gm - bb2*49;
                        int tap = kk >> 9, c = kk & 511;
                        int ii = pos/7 + tap/3 - 1, jj = pos%7 + tap%3 - 1;
                        if (ii >= 0 && ii < 7 && jj >= 0 && jj < 7)
                            v = *(const float4*)(A + ((size_t)bb2*49 + ii*7 + jj)*512 + c);
                    }
                }
                ra[it] = v;
            }
            rb = *(const float4*)(Bm + (size_t)(k0n + bkr)*N + n0 + bnr*4);
        }

        // compute on smem tile
#pragma unroll
        for (int k8 = 0; k8 < 2; k8++) {
            uint32_t af[2][4], bf[4][2];
#pragma unroll
            for (int i = 0; i < 2; i++) {
                int mrow = wm + i*16 + g;
                af[i][0] = __float_as_uint(As[(k8*8 + t4)*ASTR + mrow]);
                af[i][1] = __float_as_uint(As[(k8*8 + t4)*ASTR + mrow + 8]);
                af[i][2] = __float_as_uint(As[(k8*8 + t4 + 4)*ASTR + mrow]);
                af[i][3] = __float_as_uint(As[(k8*8 + t4 + 4)*ASTR + mrow + 8]);
            }
#pragma unroll
            for (int j = 0; j < 4; j++) {
                int ncol = wn + j*8 + g;
                bf[j][0] = __float_as_uint(Bs[(k8*8 + t4)*BSTR + ncol]);
                bf[j][1] = __float_as_uint(Bs[(k8*8 + t4 + 4)*BSTR + ncol]);
            }
#pragma unroll
            for (int i = 0; i < 2; i++)
#pragma unroll
                for (int j = 0; j < 4; j++)
                    mma_tf32(acc[i][j], af[i][0], af[i][1], af[i][2], af[i][3],
                             bf[j][0], bf[j][1]);
        }
        __syncthreads();
    }

    // ---- epilogue ----
#pragma unroll
    for (int i = 0; i < 2; i++) {
        int mbase = m0 + wm + i*16 + g;
#pragma unroll
        for (int half = 0; half < 2; half++) {
            int gm = mbase + half*8;
            if (gm < M) {
#pragma unroll
                for (int j = 0; j < 4; j++) {
                    int gn = n0 + wn + j*8 + t4*2;
                    float v0 = acc[i][j][half*2 + 0];
                    float v1 = acc[i][j][half*2 + 1];
                    if (ATOMIC) {
                        if (blockIdx.z == 0 && bias) { v0 += bias[gn]; v1 += bias[gn + 1]; }
                        atomicAdd(&C[(size_t)gm*N + gn],     v0);
                        atomicAdd(&C[(size_t)gm*N + gn + 1], v1);
                    } else {
                        if (bias) { v0 += bias[gn]; v1 += bias[gn + 1]; }
                        C[(size_t)gm*N + gn]     = v0;
                        C[(size_t)gm*N + gn + 1] = v1;
                    }
                }
            }
        }
    }
}

// ---------------- batchnorm stats + finalize + eq/ek/ev ----------------
__global__ void rea_bn_stats() {
    __shared__ float ss[512], sq[512];
    int tid = threadIdx.x;
    for (int c = tid; c < 512; c += 256) { ss[c] = 0.f; sq[c] = 0.f; }
    __syncthreads();
    int r0 = blockIdx.x*32;
    for (int r = r0; r < r0 + 32; r++) {
        for (int c = tid; c < 512; c += 256) {
            float v = g_hconv[(size_t)r*512 + c];
            ss[c] += v; sq[c] += v*v;
        }
    }
    __syncthreads();
    for (int c = tid; c < 512; c += 256) {
        atomicAdd(&g_sums[c], ss[c]);
        atomicAdd(&g_sums[512 + c], sq[c]);
    }
}

__global__ void rea_bn_fin() {
    int t = threadIdx.x;
    float s = g_sums[t], q = g_sums[512 + t];
    float mu = s * (1.f/1568.f);
    float var = q * (1.f/1568.f) - mu*mu;
    g_mu[t] = mu;
    g_is[t] = rsqrtf(var + EPSV_);
}

__global__ void rea_eqkv(const float* __restrict__ Q, const float* __restrict__ Kin,
                         const float* __restrict__ Vin) {
    int idx = blockIdx.x*blockDim.x + threadIdx.x;
    if (idx >= MM_*DD_) return;
    int c = idx & 511;
    float xn = (g_hconv[idx] - g_mu[c]) * g_is[c];
    xn = fmaxf(xn, 0.f);
    g_eq[idx] = to_tf32(xn + Q[idx]);
    g_ek[idx] = to_tf32(xn + Kin[idx]);
    g_ev[idx] = to_tf32(xn + Vin[idx]);
}

// ---------------- per-pair gate kernel ----------------
__global__ void rea_pair(const float* __restrict__ Wc2, const float* __restrict__ bc1,
                         const float* __restrict__ gc, const float* __restrict__ bcln,
                         const float* __restrict__ bc2, const float* __restrict__ br1,
                         const float* __restrict__ gr, const float* __restrict__ brln) {
    __shared__ float s_pa1[256], s_gc[256], s_bcl[256];
    __shared__ float s_par[512], s_gr[512], s_brl[512], s_w2g[512];
    __shared__ float s_wc2t[14*256];
    __shared__ float s_bc2[16], s_reg[16];
    int m = blockIdx.x;
    int b = m / 49;
    int t = threadIdx.x;
    const float* eqr = g_eqcat + (size_t)m*1280;
    s_pa1[t] = eqr[512 + t] + bc1[t];
    s_gc[t] = gc[t]; s_bcl[t] = bcln[t];
    for (int j = t; j < 512; j += 256) {
        s_par[j] = eqr[768 + j] + br1[j];
        s_gr[j] = gr[j]; s_brl[j] = brln[j]; s_w2g[j] = g_wr2g[j];
    }
    for (int idx = t; idx < 14*256; idx += 256) {
        int tt = idx >> 8, j = idx & 255;
        s_wc2t[idx] = Wc2[j*14 + tt];
    }
    if (t < NRELV_) { s_bc2[t] = bc2[t]; s_reg[t] = g_reg[t]; }
    __syncthreads();
    float c0 = g_c0[0];
    int w = t >> 5, l = t & 31;
    for (int k = w; k < 49; k += 8) {
        const float* ekr = g_ekcat + (size_t)(b*49 + k)*1280;
        // ---- channel-scorer branch: LN(256) -> relu -> @Wc2 -> softmax(14) ----
        float xc[8]; float s = 0.f;
#pragma unroll
        for (int jj = 0; jj < 8; jj++) { int j = l + 32*jj; xc[jj] = s_pa1[j] + ekr[512 + j]; s += xc[jj]; }
        s = wsum(s);
        float mean = s * (1.f/256.f);
        float vs = 0.f;
#pragma unroll
        for (int jj = 0; jj < 8; jj++) { float d = xc[jj] - mean; vs += d*d; }
        vs = wsum(vs);
        float rs = rsqrtf(vs*(1.f/256.f) + EPSV_);
        float lg[14];
#pragma unroll
        for (int tt = 0; tt < 14; tt++) lg[tt] = 0.f;
#pragma unroll
        for (int jj = 0; jj < 8; jj++) {
            int j = l + 32*jj;
            float y = (xc[jj] - mean)*rs*s_gc[j] + s_bcl[j];
            y = fmaxf(y, 0.f);
#pragma unroll
            for (int tt = 0; tt < 14; tt++) lg[tt] += y * s_wc2t[tt*256 + j];
        }
#pragma unroll
        for (int o = 16; o > 0; o >>= 1) {
#pragma unroll
            for (int tt = 0; tt < 14; tt++) lg[tt] += __shfl_xor_sync(0xffffffffu, lg[tt], o);
        }
        float mx = -1e30f;
#pragma unroll
        for (int tt = 0; tt < 14; tt++) { lg[tt] += s_bc2[tt]; mx = fmaxf(mx, lg[tt]); }
        float se = 0.f, dg = 0.f;
#pragma unroll
        for (int tt = 0; tt < 14; tt++) { float e = expf(lg[tt] - mx); se += e; dg += e*s_reg[tt]; }
        float proj = dg / se * (1.f/(1.f + 1e-8f));   // top_k over all 14 == identity
        // ---- relation branch: LN(512) -> relu -> dot(wr2g) ----
        float xr[16]; float sr = 0.f;
#pragma unroll
        for (int jj = 0; jj < 16; jj++) { int j = l + 32*jj; xr[jj] = s_par[j] + ekr[768 + j]; sr += xr[jj]; }
        sr = wsum(sr);
        float mr = sr * (1.f/512.f);
        float vr = 0.f;
#pragma unroll
        for (int jj = 0; jj < 16; jj++) { float d = xr[jj] - mr; vr += d*d; }
        vr = wsum(vr);
        float rsr = rsqrtf(vr*(1.f/512.f) + EPSV_);
        float dr = 0.f;
#pragma unroll
        for (int jj = 0; jj < 16; jj++) {
            int j = l + 32*jj;
            float y = (xr[jj] - mr)*rsr*s_gr[j] + s_brl[j];
            y = fmaxf(y, 0.f);
            dr += y * s_w2g[j];
        }
        dr = wsum(dr);
        if (l == 0) {
            float ga = dr + proj + c0;
            g_gate[(size_t)m*49 + k] = 1.f/(1.f + expf(-ga));
        }
    }
}

// ---------------- attention: logits * (1+gate), softmax(49), @V ----------------
__global__ void rea_attn(float* __restrict__ out) {
    int m = blockIdx.x, b = m / 49;
    int h = threadIdx.x >> 5, l = threadIdx.x & 31;
    __shared__ float lg[8][64];
    __shared__ float gs[49];
    if (threadIdx.x < 49) gs[threadIdx.x] = g_gate[(size_t)m*49 + threadIdx.x];
    float2 q2 = *(const float2*)(g_eqcat + (size_t)m*1280 + h*64 + l*2);
    __syncthreads();
    for (int k = 0; k < 49; k++) {
        float2 k2 = *(const float2*)(g_ekcat + (size_t)(b*49 + k)*1280 + h*64 + l*2);
        float d = q2.x*k2.x + q2.y*k2.y;
        d = wsum(d);
        if (l == 0) lg[h][k] = d * SCALEV_ * (1.f + gs[k]);
    }
    __syncwarp();
    float v0 = lg[h][l];
    float v1 = (l < 17) ? lg[h][l + 32] : -1e30f;
    float mx = fmaxf(v0, v1);
#pragma unroll
    for (int o = 16; o > 0; o >>= 1) mx = fmaxf(mx, __shfl_xor_sync(0xffffffffu, mx, o));
    float e0 = expf(v0 - mx);
    float e1 = (l < 17) ? expf(v1 - mx) : 0.f;
    float ssum = wsum(e0 + e1);
    float inv = 1.f / ssum;
    lg[h][l] = e0 * inv;
    if (l < 17) lg[h][l + 32] = e1 * inv;
    __syncwarp();
    float2 acc = make_float2(0.f, 0.f);
    for (int k = 0; k < 49; k++) {
        float wv = lg[h][k];
        float2 v2 = *(const float2*)(g_v + (size_t)(b*49 + k)*512 + h*64 + l*2);
        acc.x += wv*v2.x; acc.y += wv*v2.y;
    }
    // round: this is the A operand of the final tf32 GEMM
    out[(size_t)m*512 + h*64 + l*2]     = to_tf32(acc.x);
    out[(size_t)m*512 + h*64 + l*2 + 1] = to_tf32(acc.y);
}

// ---------------- launch ----------------
extern "C" void kernel_launch(void* const* d_in, const int* in_sizes, int n_in,
                              void* d_out, int out_size) {
    const float* Q     = (const float*)d_in[0];
    const float* Kin   = (const float*)d_in[1];
    const float* Vin   = (const float*)d_in[2];
    const float* Wq    = (const float*)d_in[3];
    const float* bq    = (const float*)d_in[4];
    const float* Wk    = (const float*)d_in[5];
    const float* bk    = (const float*)d_in[6];
    const float* Wv    = (const float*)d_in[7];
    const float* bv    = (const float*)d_in[8];
    const float* Wo    = (const float*)d_in[9];
    const float* bo    = (const float*)d_in[10];
    const float* rel   = (const float*)d_in[11];
    const float* Wproj = (const float*)d_in[12];
    const float* bproj = (const float*)d_in[13];
    const float* Wgate = (const float*)d_in[14];
    const float* bgate = (const float*)d_in[15];
    const float* Wc1   = (const float*)d_in[16];
    const float* bc1   = (const float*)d_in[17];
    const float* gc    = (const float*)d_in[18];
    const float* bcln  = (const float*)d_in[19];
    const float* Wc2   = (const float*)d_in[20];
    const float* bc2   = (const float*)d_in[21];
    const float* Wr1   = (const float*)d_in[22];
    const float* br1   = (const float*)d_in[23];
    const float* gr    = (const float*)d_in[24];
    const float* brln  = (const float*)d_in[25];
    const float* Wr2   = (const float*)d_in[26];
    const float* br2   = (const float*)d_in[27];
    const float* convW = (const float*)d_in[28];
    const float* convb = (const float*)d_in[29];

    void *p_hconv, *p_qr, *p_eq, *p_ek, *p_ev, *p_eqcat, *p_ekcat, *p_v, *p_att;
    void *p_convWt, *p_Bq, *p_Bk, *p_Wvr, *p_Wor, *p_biasq, *p_biask;
    cudaGetSymbolAddress(&p_hconv, g_hconv);
    cudaGetSymbolAddress(&p_qr, g_qr);
    cudaGetSymbolAddress(&p_eq, g_eq);
    cudaGetSymbolAddress(&p_ek, g_ek);
    cudaGetSymbolAddress(&p_ev, g_ev);
    cudaGetSymbolAddress(&p_eqcat, g_eqcat);
    cudaGetSymbolAddress(&p_ekcat, g_ekcat);
    cudaGetSymbolAddress(&p_v, g_v);
    cudaGetSymbolAddress(&p_att, g_att);
    cudaGetSymbolAddress(&p_convWt, g_convWt);
    cudaGetSymbolAddress(&p_Bq, g_Bq);
    cudaGetSymbolAddress(&p_Bk, g_Bk);
    cudaGetSymbolAddress(&p_Wvr, g_Wvr);
    cudaGetSymbolAddress(&p_Wor, g_Wor);
    cudaGetSymbolAddress(&p_biasq, g_biasq);
    cudaGetSymbolAddress(&p_biask, g_biask);

    rea_zero_stats<<<4, 256>>>();
    rea_zero_hconv<<<(MM_*DD_ + 511)/512, 512>>>();
    rea_k0<<<1, 512>>>(Wr2, Wproj, Wgate, rel, br2, bproj, bgate);
    rea_repack_conv<<<(9*512*512 + 255)/256, 256>>>(convW);
    rea_repack_bcat<<<(512*1280 + 255)/256, 256>>>(Wq, Wk, Wc1, Wr1, bq, bk);
    rea_round_w<<<(512*512 + 255)/256, 256>>>(Wv, Wo);
    rea_round_q<<<(MM_*DD_ + 255)/256, 256>>>(Q);

    // conv3x3 as implicit GEMM (tf32 tensor cores, split-K=4, atomic accumulate):
    // [1568,512] += im2col(q_r)[1568, 4*1152] @ convWt[4608,512] (+ convb on z==0)
    rea_mma<true, true><<<dim3(8, 13, 4), 256>>>(
        (const float*)p_qr, (const float*)p_convWt, convb, (float*)p_hconv,
        MM_, 512, 1152);

    rea_bn_stats<<<49, 256>>>();
    rea_bn_fin<<<1, 512>>>();
    rea_eqkv<<<(MM_*DD_ + 255)/256, 256>>>(Q, Kin, Vin);

    // fused token projections: eq @ [Wq | Wc1_top | Wr1_top], ek @ [Wk | Wc1_bot | Wr1_bot]
    rea_mma<false, false><<<dim3(20, 13, 1), 256>>>(
        (const float*)p_eq, (const float*)p_Bq, (const float*)p_biasq,
        (float*)p_eqcat, MM_, 1280, 512);
    rea_mma<false, false><<<dim3(20, 13, 1), 256>>>(
        (const float*)p_ek, (const float*)p_Bk, (const float*)p_biask,
        (float*)p_ekcat, MM_, 1280, 512);
    rea_mma<false, false><<<dim3(8, 13, 1), 256>>>(
        (const float*)p_ev, (const float*)p_Wvr, bv, (float*)p_v,
        MM_, 512, 512);

    rea_pair<<<MM_, 256>>>(Wc2, bc1, gc, bcln, bc2, br1, gr, brln);
    rea_attn<<<MM_, 256>>>((float*)p_att);

    rea_mma<false, false><<<dim3(8, 13, 1), 256>>>(
        (const float*)p_att, (const float*)p_Wor, bo, (float*)d_out,
        MM_, 512, 512);
}

// round 3
// speedup vs baseline: 1.9936x; 1.2513x over previous
#include <cuda_runtime.h>
#include <math.h>
#include <stdint.h>

// Problem constants
#define BB_ 32
#define NN_ 49
#define DD_ 512
#define MM_ (BB_*NN_)      // 1568
#define NRELV_ 14
#define EPSV_ 1e-5f
#define SCALEV_ 0.125f     // 1/sqrt(64)

// ---------------- device scratch (no allocations allowed) ----------------
__device__ __align__(256) float g_hconv[MM_*DD_];
__device__ __align__(256) float g_qr[MM_*DD_];
__device__ __align__(256) float g_eq[MM_*DD_];
__device__ __align__(256) float g_ek[MM_*DD_];
__device__ __align__(256) float g_ev[MM_*DD_];
__device__ __align__(256) float g_eqcat[MM_*1280];
__device__ __align__(256) float g_ekcat[MM_*1280];
__device__ __align__(256) float g_v[MM_*DD_];
__device__ __align__(256) float g_att[MM_*DD_];
__device__ __align__(256) float g_convWt[9*512*512];
__device__ __align__(256) float g_Bq[512*1280];
__device__ __align__(256) float g_Bk[512*1280];
__device__ __align__(256) float g_Wvr[512*512];
__device__ __align__(256) float g_Wor[512*512];
__device__ __align__(256) float g_biasq[1280];
__device__ __align__(256) float g_biask[1280];
__device__ float g_sums[1024];
__device__ float g_mu[512];
__device__ float g_is[512];
__device__ float g_wr2g[512];
__device__ float g_reg[NRELV_];
__device__ float g_c0[1];
__device__ float g_gate[MM_*NN_];

__device__ __forceinline__ float wsum(float v) {
#pragma unroll
    for (int o = 16; o > 0; o >>= 1) v += __shfl_xor_sync(0xffffffffu, v, o);
    return v;
}

__device__ __forceinline__ float to_tf32(float x) {
    uint32_t u;
    asm("cvt.rna.tf32.f32 %0, %1;" : "=r"(u) : "f"(x));
    return __uint_as_float(u);
}

__device__ __forceinline__ void mma_tf32(float* c,
                                         uint32_t a0, uint32_t a1, uint32_t a2, uint32_t a3,
                                         uint32_t b0, uint32_t b1) {
    asm volatile("mma.sync.aligned.m16n8k8.row.col.f32.tf32.tf32.f32 "
                 "{%0,%1,%2,%3}, {%4,%5,%6,%7}, {%8,%9}, {%0,%1,%2,%3};"
                 : "+f"(c[0]), "+f"(c[1]), "+f"(c[2]), "+f"(c[3])
                 : "r"(a0), "r"(a1), "r"(a2), "r"(a3), "r"(b0), "r"(b1));
}

__device__ __forceinline__ void cp16(uint32_t dst, const float* src, bool pred) {
    int sz = pred ? 16 : 0;
    asm volatile("cp.async.cg.shared.global [%0], [%1], 16, %2;\n"
                 :: "r"(dst), "l"(src), "r"(sz));
}
#define CP_COMMIT() asm volatile("cp.async.commit_group;")
#define CP_WAIT1()  asm volatile("cp.async.wait_group 1;")

// ---------------- tiny precompute: folded gate vectors ----------------
__global__ void rea_k0(const float* __restrict__ Wr2, const float* __restrict__ Wproj,
                       const float* __restrict__ Wg, const float* __restrict__ rel,
                       const float* __restrict__ br2, const float* __restrict__ bproj,
                       const float* __restrict__ bgate) {
    __shared__ float wg_s[512];
    __shared__ float wpg_s[64];
    int t = threadIdx.x;
    wg_s[t] = Wg[t];
    __syncthreads();
    float a = 0.f;
    for (int j = 0; j < 512; j++) a += Wr2[(size_t)t*512 + j] * wg_s[j];
    g_wr2g[t] = a;
    if (t < 64) {
        float s = 0.f;
        for (int j = 0; j < 512; j++) s += Wproj[(size_t)t*512 + j] * wg_s[j];
        wpg_s[t] = s;
    }
    __syncthreads();
    if (t < NRELV_) {
        float s = 0.f;
        for (int d = 0; d < 64; d++) s += rel[t*64 + d] * wpg_s[d];
        g_reg[t] = s;
    }
    if (t == 0) {
        float s = bgate[0];
        for (int j = 0; j < 512; j++) s += (br2[j] + bproj[j]) * wg_s[j];
        g_c0[0] = s;
    }
}

// ---------------- weight repacks (rounded to tf32) ----------------
// convW [O=512][C=512][tap=9] -> g_convWt [tap][C][O], smem-transposed tiles.
__global__ void rea_repack_conv(const float* __restrict__ convW) {
    __shared__ float t[32][33];
    int tap = blockIdx.z;
    int o0 = blockIdx.x*32, c0 = blockIdx.y*32;
    int tx = threadIdx.x & 31, ty = threadIdx.x >> 5;  // ty 0..7
#pragma unroll
    for (int k = 0; k < 4; k++) {
        int o = o0 + ty + k*8;
        t[ty + k*8][tx] = to_tf32(convW[((size_t)o*512 + (c0 + tx))*9 + tap]);
    }
    __syncthreads();
#pragma unroll
    for (int k = 0; k < 4; k++) {
        int c = c0 + ty + k*8;
        g_convWt[(size_t)tap*262144 + (size_t)c*512 + o0 + tx] = t[tx][ty + k*8];
    }
}

__global__ void rea_repack_bcat(const float* __restrict__ Wq, const float* __restrict__ Wk,
                                const float* __restrict__ Wc1, const float* __restrict__ Wr1,
                                const float* __restrict__ bq, const float* __restrict__ bk) {
    int idx = blockIdx.x*blockDim.x + threadIdx.x;
    if (idx < 512*1280) {
        int k = idx / 1280, n = idx - k*1280;
        float vq, vk;
        if (n < 512)       { vq = Wq[(size_t)k*512 + n];              vk = Wk[(size_t)k*512 + n]; }
        else if (n < 768)  { vq = Wc1[(size_t)k*256 + (n-512)];       vk = Wc1[(size_t)(k+512)*256 + (n-512)]; }
        else               { vq = Wr1[(size_t)k*512 + (n-768)];       vk = Wr1[(size_t)(k+512)*512 + (n-768)]; }
        g_Bq[idx] = to_tf32(vq); g_Bk[idx] = to_tf32(vk);
    }
    if (idx < 1280) {
        g_biasq[idx] = idx < 512 ? bq[idx] : 0.f;
        g_biask[idx] = idx < 512 ? bk[idx] : 0.f;
    }
}

__global__ void rea_round_w(const float* __restrict__ Wv, const float* __restrict__ Wo) {
    int idx = blockIdx.x*blockDim.x + threadIdx.x;
    if (idx >= 512*512) return;
    g_Wvr[idx] = to_tf32(Wv[idx]);
    g_Wor[idx] = to_tf32(Wo[idx]);
}

__global__ void rea_round_q(const float* __restrict__ Q) {
    int idx = blockIdx.x*blockDim.x + threadIdx.x;
    if (idx >= MM_*DD_) return;
    g_qr[idx] = to_tf32(Q[idx]);
}

__global__ void rea_zero() {
    int i = blockIdx.x*blockDim.x + threadIdx.x;
    if (i < 1024) g_sums[i] = 0.f;
    if (i < MM_*DD_) g_hconv[i] = 0.f;
}

// ---------------- TF32 tensor-core GEMM core ----------------
// Block tile 128x128, BK=16, 256 threads = 8 warps (2M x 4N), warp tile 64x32.
// cp.async double-buffered. A row-major [M,lda] (implicit im2col when CONV),
// B row-major [K,N]. ATOMIC: atomicAdd into pre-zeroed C; bias only on z==0.
#define BMT 128
#define BNT 128
#define BKT 16
#define APAD 20
#define BPAD 136
#define SZA (BMT*APAD*4)
#define SZB (BKT*BPAD*4)

template <bool CONV, bool ATOMIC>
__device__ __forceinline__ void gemm_core(
    const float* __restrict__ A, const float* __restrict__ Bm,
    const float* __restrict__ bias, float* __restrict__ C,
    int M, int N, int lda, int kbase, int KT,
    float* AsB, float* BsB) {

    int tid = threadIdx.x;
    int lane = tid & 31, warp = tid >> 5;
    int g = lane >> 2, t4 = lane & 3;
    int wm = (warp & 1) * 64, wn = (warp >> 1) * 32;
    int m0 = blockIdx.y * BMT, n0 = blockIdx.x * BNT;

    uint32_t sA = (uint32_t)__cvta_generic_to_shared(AsB);
    uint32_t sB = (uint32_t)__cvta_generic_to_shared(BsB);

    float acc[4][4][4];
#pragma unroll
    for (int i = 0; i < 4; i++)
#pragma unroll
        for (int j = 0; j < 4; j++)
#pragma unroll
            for (int q = 0; q < 4; q++) acc[i][j][q] = 0.f;

    // per-thread load assignments (2 A chunks + 2 B chunks of 16B each)
    auto load_tile = [&](int kt, int buf) {
        int k0 = kbase + kt * BKT;
#pragma unroll
        for (int h = 0; h < 2; h++) {
            int c = tid + h*256;
            int m = c >> 2, kg = c & 3;
            int gm = m0 + m;
            int kk = k0 + kg*4;
            const float* src;
            bool pred;
            if (!CONV) {
                pred = gm < M;
                src = A + (pred ? ((size_t)gm*lda + kk) : 0);
            } else {
                int bb2 = gm / 49, pos = gm - bb2*49;
                int tap = kk >> 9, ch = kk & 511;
                int pr = pos / 7;
                int ii = pr + tap/3 - 1;
                int jj = (pos - pr*7) + (tap - (tap/3)*3) - 1;
                pred = (gm < M) & ((unsigned)ii < 7u) & ((unsigned)jj < 7u);
                size_t off = pred ? (((size_t)(bb2*49 + ii*7 + jj))*512 + ch) : 0;
                src = A + off;
            }
            cp16(sA + buf*SZA + (m*APAD + kg*4)*4, src, pred);
        }
#pragma unroll
        for (int h = 0; h < 2; h++) {
            int c = tid + h*256;
            int kr = c >> 5, ng = c & 31;
            const float* src = Bm + (size_t)(k0 + kr)*N + n0 + ng*4;
            cp16(sB + buf*SZB + (kr*BPAD + ng*4)*4, src, true);
        }
    };

    load_tile(0, 0);
    CP_COMMIT();

    for (int kt = 0; kt < KT; kt++) {
        if (kt + 1 < KT) load_tile(kt + 1, (kt + 1) & 1);
        CP_COMMIT();
        CP_WAIT1();
        __syncthreads();
        const float* as = AsB + (kt & 1)*(BMT*APAD);
        const float* bs = BsB + (kt & 1)*(BKT*BPAD);
#pragma unroll
        for (int k8 = 0; k8 < 2; k8++) {
            uint32_t af[4][4], bf[4][2];
#pragma unroll
            for (int i = 0; i < 4; i++) {
                int mrow = wm + i*16 + g;
                af[i][0] = __float_as_uint(as[mrow*APAD + k8*8 + t4]);
                af[i][1] = __float_as_uint(as[(mrow + 8)*APAD + k8*8 + t4]);
                af[i][2] = __float_as_uint(as[mrow*APAD + k8*8 + t4 + 4]);
                af[i][3] = __float_as_uint(as[(mrow + 8)*APAD + k8*8 + t4 + 4]);
            }
#pragma unroll
            for (int j = 0; j < 4; j++) {
                int nc = wn + j*8 + g;
                bf[j][0] = __float_as_uint(bs[(k8*8 + t4)*BPAD + nc]);
                bf[j][1] = __float_as_uint(bs[(k8*8 + t4 + 4)*BPAD + nc]);
            }
#pragma unroll
            for (int i = 0; i < 4; i++)
#pragma unroll
                for (int j = 0; j < 4; j++)
                    mma_tf32(acc[i][j], af[i][0], af[i][1], af[i][2], af[i][3],
                             bf[j][0], bf[j][1]);
        }
        __syncthreads();
    }

    // epilogue
#pragma unroll
    for (int i = 0; i < 4; i++) {
        int mbase = m0 + wm + i*16 + g;
#pragma unroll
        for (int half = 0; half < 2; half++) {
            int gm = mbase + half*8;
            if (gm < M) {
#pragma unroll
                for (int j = 0; j < 4; j++) {
                    int gn = n0 + wn + j*8 + t4*2;
                    float v0 = acc[i][j][half*2 + 0];
                    float v1 = acc[i][j][half*2 + 1];
                    if (ATOMIC) {
                        if (blockIdx.z == 0 && bias) { v0 += bias[gn]; v1 += bias[gn + 1]; }
                        atomicAdd(&C[(size_t)gm*N + gn],     v0);
                        atomicAdd(&C[(size_t)gm*N + gn + 1], v1);
                    } else {
                        if (bias) { v0 += bias[gn]; v1 += bias[gn + 1]; }
                        C[(size_t)gm*N + gn]     = v0;
                        C[(size_t)gm*N + gn + 1] = v1;
                    }
                }
            }
        }
    }
}

// conv as implicit GEMM, split-K over blockIdx.z
__global__ void __launch_bounds__(256, 2)
rea_gconv(const float* __restrict__ A, const float* __restrict__ Bm,
          const float* __restrict__ bias, float* __restrict__ C) {
    __shared__ float AsB[2*BMT*APAD];
    __shared__ float BsB[2*BKT*BPAD];
    gemm_core<true, true>(A, Bm, bias, C, MM_, 512, 4608,
                          blockIdx.z*1152, 72, AsB, BsB);
}

// batched eq/ek/ev projections over blockIdx.z
__global__ void __launch_bounds__(256, 2)
rea_gqkv(const float* __restrict__ bv) {
    __shared__ float AsB[2*BMT*APAD];
    __shared__ float BsB[2*BKT*BPAD];
    int z = blockIdx.z;
    if (z == 2 && blockIdx.x >= 4) return;
    const float* A    = z == 0 ? g_eq    : z == 1 ? g_ek    : g_ev;
    const float* Bm   = z == 0 ? g_Bq    : z == 1 ? g_Bk    : g_Wvr;
    const float* bias = z == 0 ? g_biasq : z == 1 ? g_biask : bv;
    float*       C    = z == 0 ? g_eqcat : z == 1 ? g_ekcat : g_v;
    int N = z < 2 ? 1280 : 512;
    gemm_core<false, false>(A, Bm, bias, C, MM_, N, 512, 0, 32, AsB, BsB);
}

__global__ void __launch_bounds__(256, 2)
rea_gout(const float* __restrict__ A, const float* __restrict__ Bm,
         const float* __restrict__ bias, float* __restrict__ C) {
    __shared__ float AsB[2*BMT*APAD];
    __shared__ float BsB[2*BKT*BPAD];
    gemm_core<false, false>(A, Bm, bias, C, MM_, 512, 512, 0, 32, AsB, BsB);
}

// ---------------- batchnorm stats + finalize + eq/ek/ev ----------------
__global__ void rea_bn_stats() {
    __shared__ float ss[512], sq[512];
    int tid = threadIdx.x;
    for (int c = tid; c < 512; c += 256) { ss[c] = 0.f; sq[c] = 0.f; }
    __syncthreads();
    int r0 = blockIdx.x*32;
    for (int r = r0; r < r0 + 32; r++) {
        for (int c = tid; c < 512; c += 256) {
            float v = g_hconv[(size_t)r*512 + c];
            ss[c] += v; sq[c] += v*v;
        }
    }
    __syncthreads();
    for (int c = tid; c < 512; c += 256) {
        atomicAdd(&g_sums[c], ss[c]);
        atomicAdd(&g_sums[512 + c], sq[c]);
    }
}

__global__ void rea_bn_fin() {
    int t = threadIdx.x;
    float s = g_sums[t], q = g_sums[512 + t];
    float mu = s * (1.f/1568.f);
    float var = q * (1.f/1568.f) - mu*mu;
    g_mu[t] = mu;
    g_is[t] = rsqrtf(var + EPSV_);
}

__global__ void rea_eqkv(const float* __restrict__ Q, const float* __restrict__ Kin,
                         const float* __restrict__ Vin) {
    int idx = blockIdx.x*blockDim.x + threadIdx.x;
    if (idx >= MM_*DD_) return;
    int c = idx & 511;
    float xn = (g_hconv[idx] - g_mu[c]) * g_is[c];
    xn = fmaxf(xn, 0.f);
    g_eq[idx] = to_tf32(xn + Q[idx]);
    g_ek[idx] = to_tf32(xn + Kin[idx]);
    g_ev[idx] = to_tf32(xn + Vin[idx]);
}

// ---------------- per-pair gate kernel ----------------
__global__ void rea_pair(const float* __restrict__ Wc2, const float* __restrict__ bc1,
                         const float* __restrict__ gc, const float* __restrict__ bcln,
                         const float* __restrict__ bc2, const float* __restrict__ br1,
                         const float* __restrict__ gr, const float* __restrict__ brln) {
    __shared__ float s_pa1[256], s_gc[256], s_bcl[256];
    __shared__ float s_par[512], s_gr[512], s_brl[512], s_w2g[512];
    __shared__ float s_wc2t[14*256];
    __shared__ float s_bc2[16], s_reg[16];
    int m = blockIdx.x;
    int b = m / 49;
    int t = threadIdx.x;
    const float* eqr = g_eqcat + (size_t)m*1280;
    s_pa1[t] = eqr[512 + t] + bc1[t];
    s_gc[t] = gc[t]; s_bcl[t] = bcln[t];
    for (int j = t; j < 512; j += 256) {
        s_par[j] = eqr[768 + j] + br1[j];
        s_gr[j] = gr[j]; s_brl[j] = brln[j]; s_w2g[j] = g_wr2g[j];
    }
    for (int idx = t; idx < 14*256; idx += 256) {
        int tt = idx >> 8, j = idx & 255;
        s_wc2t[idx] = Wc2[j*14 + tt];
    }
    if (t < NRELV_) { s_bc2[t] = bc2[t]; s_reg[t] = g_reg[t]; }
    __syncthreads();
    float c0 = g_c0[0];
    int w = t >> 5, l = t & 31;
    for (int k = w; k < 49; k += 8) {
        const float* ekr = g_ekcat + (size_t)(b*49 + k)*1280;
        float xc[8]; float s = 0.f;
#pragma unroll
        for (int jj = 0; jj < 8; jj++) { int j = l + 32*jj; xc[jj] = s_pa1[j] + ekr[512 + j]; s += xc[jj]; }
        s = wsum(s);
        float mean = s * (1.f/256.f);
        float vs = 0.f;
#pragma unroll
        for (int jj = 0; jj < 8; jj++) { float d = xc[jj] - mean; vs += d*d; }
        vs = wsum(vs);
        float rs = rsqrtf(vs*(1.f/256.f) + EPSV_);
        float lg[14];
#pragma unroll
        for (int tt = 0; tt < 14; tt++) lg[tt] = 0.f;
#pragma unroll
        for (int jj = 0; jj < 8; jj++) {
            int j = l + 32*jj;
            float y = (xc[jj] - mean)*rs*s_gc[j] + s_bcl[j];
            y = fmaxf(y, 0.f);
#pragma unroll
            for (int tt = 0; tt < 14; tt++) lg[tt] += y * s_wc2t[tt*256 + j];
        }
#pragma unroll
        for (int o = 16; o > 0; o >>= 1) {
#pragma unroll
            for (int tt = 0; tt < 14; tt++) lg[tt] += __shfl_xor_sync(0xffffffffu, lg[tt], o);
        }
        float mx = -1e30f;
#pragma unroll
        for (int tt = 0; tt < 14; tt++) { lg[tt] += s_bc2[tt]; mx = fmaxf(mx, lg[tt]); }
        float se = 0.f, dg = 0.f;
#pragma unroll
        for (int tt = 0; tt < 14; tt++) { float e = expf(lg[tt] - mx); se += e; dg += e*s_reg[tt]; }
        float proj = dg / se * (1.f/(1.f + 1e-8f));
        float xr[16]; float sr = 0.f;
#pragma unroll
        for (int jj = 0; jj < 16; jj++) { int j = l + 32*jj; xr[jj] = s_par[j] + ekr[768 + j]; sr += xr[jj]; }
        sr = wsum(sr);
        float mr = sr * (1.f/512.f);
        float vr = 0.f;
#pragma unroll
        for (int jj = 0; jj < 16; jj++) { float d = xr[jj] - mr; vr += d*d; }
        vr = wsum(vr);
        float rsr = rsqrtf(vr*(1.f/512.f) + EPSV_);
        float dr = 0.f;
#pragma unroll
        for (int jj = 0; jj < 16; jj++) {
            int j = l + 32*jj;
            float y = (xr[jj] - mr)*rsr*s_gr[j] + s_brl[j];
            y = fmaxf(y, 0.f);
            dr += y * s_w2g[j];
        }
        dr = wsum(dr);
        if (l == 0) {
            float ga = dr + proj + c0;
            g_gate[(size_t)m*49 + k] = 1.f/(1.f + expf(-ga));
        }
    }
}

// ---------------- attention: logits * (1+gate), softmax(49), @V ----------------
__global__ void rea_attn(float* __restrict__ out) {
    int m = blockIdx.x, b = m / 49;
    int h = threadIdx.x >> 5, l = threadIdx.x & 31;
    __shared__ float lg[8][64];
    __shared__ float gs[49];
    if (threadIdx.x < 49) gs[threadIdx.x] = g_gate[(size_t)m*49 + threadIdx.x];
    float2 q2 = *(const float2*)(g_eqcat + (size_t)m*1280 + h*64 + l*2);
    __syncthreads();
    for (int k = 0; k < 49; k++) {
        float2 k2 = *(const float2*)(g_ekcat + (size_t)(b*49 + k)*1280 + h*64 + l*2);
        float d = q2.x*k2.x + q2.y*k2.y;
        d = wsum(d);
        if (l == 0) lg[h][k] = d * SCALEV_ * (1.f + gs[k]);
    }
    __syncwarp();
    float v0 = lg[h][l];
    float v1 = (l < 17) ? lg[h][l + 32] : -1e30f;
    float mx = fmaxf(v0, v1);
#pragma unroll
    for (int o = 16; o > 0; o >>= 1) mx = fmaxf(mx, __shfl_xor_sync(0xffffffffu, mx, o));
    float e0 = expf(v0 - mx);
    float e1 = (l < 17) ? expf(v1 - mx) : 0.f;
    float ssum = wsum(e0 + e1);
    float inv = 1.f / ssum;
    lg[h][l] = e0 * inv;
    if (l < 17) lg[h][l + 32] = e1 * inv;
    __syncwarp();
    float2 acc = make_float2(0.f, 0.f);
    for (int k = 0; k < 49; k++) {
        float wv = lg[h][k];
        float2 v2 = *(const float2*)(g_v + (size_t)(b*49 + k)*512 + h*64 + l*2);
        acc.x += wv*v2.x; acc.y += wv*v2.y;
    }
    out[(size_t)m*512 + h*64 + l*2]     = to_tf32(acc.x);
    out[(size_t)m*512 + h*64 + l*2 + 1] = to_tf32(acc.y);
}

// ---------------- launch ----------------
extern "C" void kernel_launch(void* const* d_in, const int* in_sizes, int n_in,
                              void* d_out, int out_size) {
    const float* Q     = (const float*)d_in[0];
    const float* Kin   = (const float*)d_in[1];
    const float* Vin   = (const float*)d_in[2];
    const float* Wq    = (const float*)d_in[3];
    const float* bq    = (const float*)d_in[4];
    const float* Wk    = (const float*)d_in[5];
    const float* bk    = (const float*)d_in[6];
    const float* Wv    = (const float*)d_in[7];
    const float* bv    = (const float*)d_in[8];
    const float* Wo    = (const float*)d_in[9];
    const float* bo    = (const float*)d_in[10];
    const float* rel   = (const float*)d_in[11];
    const float* Wproj = (const float*)d_in[12];
    const float* bproj = (const float*)d_in[13];
    const float* Wgate = (const float*)d_in[14];
    const float* bgate = (const float*)d_in[15];
    const float* Wc1   = (const float*)d_in[16];
    const float* bc1   = (const float*)d_in[17];
    const float* gc    = (const float*)d_in[18];
    const float* bcln  = (const float*)d_in[19];
    const float* Wc2   = (const float*)d_in[20];
    const float* bc2   = (const float*)d_in[21];
    const float* Wr1   = (const float*)d_in[22];
    const float* br1   = (const float*)d_in[23];
    const float* gr    = (const float*)d_in[24];
    const float* brln  = (const float*)d_in[25];
    const float* Wr2   = (const float*)d_in[26];
    const float* br2   = (const float*)d_in[27];
    const float* convW = (const float*)d_in[28];
    const float* convb = (const float*)d_in[29];

    void *p_hconv, *p_qr, *p_att, *p_convWt, *p_Wor;
    cudaGetSymbolAddress(&p_hconv, g_hconv);
    cudaGetSymbolAddress(&p_qr, g_qr);
    cudaGetSymbolAddress(&p_att, g_att);
    cudaGetSymbolAddress(&p_convWt, g_convWt);
    cudaGetSymbolAddress(&p_Wor, g_Wor);

    rea_zero<<<(MM_*DD_ + 511)/512, 512>>>();
    rea_k0<<<1, 512>>>(Wr2, Wproj, Wgate, rel, br2, bproj, bgate);
    rea_repack_conv<<<dim3(16, 16, 9), 256>>>(convW);
    rea_repack_bcat<<<(512*1280 + 255)/256, 256>>>(Wq, Wk, Wc1, Wr1, bq, bk);
    rea_round_w<<<(512*512 + 255)/256, 256>>>(Wv, Wo);
    rea_round_q<<<(MM_*DD_ + 255)/256, 256>>>(Q);

    // conv3x3 implicit GEMM (tf32, split-K=4, atomic accumulate)
    rea_gconv<<<dim3(4, 13, 4), 256>>>((const float*)p_qr, (const float*)p_convWt,
                                       convb, (float*)p_hconv);

    rea_bn_stats<<<49, 256>>>();
    rea_bn_fin<<<1, 512>>>();
    rea_eqkv<<<(MM_*DD_ + 255)/256, 256>>>(Q, Kin, Vin);

    // batched eq/ek/ev projections in one launch
    rea_gqkv<<<dim3(10, 13, 3), 256>>>(bv);

    rea_pair<<<MM_, 256>>>(Wc2, bc1, gc, bcln, bc2, br1, gr, brln);
    rea_attn<<<MM_, 256>>>((float*)p_att);

    rea_gout<<<dim3(4, 13), 256>>>((const float*)p_att, (const float*)p_Wor,
                                   bo, (float*)d_out);
}